// round 16
// baseline (speedup 1.0000x reference)
#include <cuda_runtime.h>
#include <cstdint>

// FINAL (R15): 2x2 Haar inverse reconstruction
//   x: (32, 4, 512, 512) f32  ->  out: (32, 1, 1024, 1024) f32
//   L0=R*a+R*b; L1=R*a-R*b; H0=R*c+R*d; H1=R*c-R*d
//   out[2h,2w]=R*(L0+H0)  out[2h,2w+1]=R*(L0-H0)
//   out[2h+1,2w]=R*(L1+H1)  out[2h+1,2w+1]=R*(L1-H1)
//
// Design (evidence from rounds 2-15):
//  - one CTA = one input row, 128 threads, 8KB smem, 26 regs
//  - reads:  4x LDG.128.cs per thread (scattered per-warp reads proved
//            optimal; all read-batching variants regressed)
//  - writes: stage 2 output rows (8KB contiguous) in smem, emit with ONE
//            cp.async.bulk carrying L2::evict_first (bulk-batched writes
//            moved DRAM 58% -> 72%; the policy added the last ~1.4pt)
//  - plateau: ~5.9 TB/s (72% of spec) = mixed 1:1 R/W touch-once ceiling;
//    occupancy/burst/persistence/read-batching levers all tested, flat.

#define RCONST 0.70710678118654752440f

static constexpr int S = 512;     // input spatial
static constexpr int NIMG = 32;   // batch

__device__ __forceinline__ void haar4(float a, float b, float c, float d,
                                      float& o00, float& o01, float& o10, float& o11) {
    float l0 = RCONST * a + RCONST * b;
    float l1 = RCONST * a - RCONST * b;
    float h0 = RCONST * c + RCONST * d;
    float h1 = RCONST * c - RCONST * d;
    o00 = RCONST * l0 + RCONST * h0;
    o01 = RCONST * l0 - RCONST * h0;
    o10 = RCONST * l1 + RCONST * h1;
    o11 = RCONST * l1 - RCONST * h1;
}

__device__ __forceinline__ uint32_t smem_u32(const void* p) {
    uint32_t a;
    asm("{ .reg .u64 t; cvta.to.shared.u64 t, %1; cvt.u32.u64 %0, t; }"
        : "=r"(a) : "l"(p));
    return a;
}

__global__ __launch_bounds__(128)
void haar_recon_kernel(const float* __restrict__ x, float* __restrict__ out) {
    // 2 output rows x 1024 floats = 8KB
    __shared__ alignas(16) float sout[2 * 2 * S];

    unsigned t  = threadIdx.x;    // 0..127 = float4 index within input row
    unsigned b  = blockIdx.x;
    unsigned h  = b & 511;        // input row
    unsigned n  = b >> 9;         // image

    const size_t cs4 = (size_t)S * S / 4;   // channel stride in float4
    const float4* base = (const float4*)(x + (size_t)n * 4 * S * S + (size_t)h * S) + t;

    // 4 independent 128-bit streaming loads (MLP=4, evict-first)
    float4 a  = __ldcs(base);
    float4 bb = __ldcs(base + cs4);
    float4 c  = __ldcs(base + 2 * cs4);
    float4 d  = __ldcs(base + 3 * cs4);

    float4 r0a, r0b, r1a, r1b;
    haar4(a.x, bb.x, c.x, d.x, r0a.x, r0a.y, r1a.x, r1a.y);
    haar4(a.y, bb.y, c.y, d.y, r0a.z, r0a.w, r1a.z, r1a.w);
    haar4(a.z, bb.z, c.z, d.z, r0b.x, r0b.y, r1b.x, r1b.y);
    haar4(a.w, bb.w, c.w, d.w, r0b.z, r0b.w, r1b.z, r1b.w);

    // stage: local row 0 = out row 2h, local row 1 = out row 2h+1
    float4* srow0 = (float4*)sout + 2 * t;
    float4* srow1 = (float4*)(sout + 2 * S) + 2 * t;
    srow0[0] = r0a;
    srow0[1] = r0b;
    srow1[0] = r1a;
    srow1[1] = r1b;

    __syncthreads();

    if (t == 0) {
        asm volatile("fence.proxy.async.shared::cta;" ::: "memory");
        // output rows 2h .. 2h+1  (8KB contiguous), evict-first in L2
        float* gdst = out + ((size_t)n * 2 * S + (size_t)2 * h) * (2 * S);
        asm volatile(
            "{\n\t"
            ".reg .b64 pol;\n\t"
            "createpolicy.fractional.L2::evict_first.b64 pol, 1.0;\n\t"
            "cp.async.bulk.global.shared::cta.bulk_group.L2::cache_hint "
            "[%0], [%1], %2, pol;\n\t"
            "}"
            :: "l"(gdst), "r"(smem_u32(sout)),
               "r"((unsigned)(2 * 2 * S * sizeof(float)))
            : "memory");
        asm volatile("cp.async.bulk.commit_group;" ::: "memory");
        asm volatile("cp.async.bulk.wait_group 0;" ::: "memory");
    }
}

extern "C" void kernel_launch(void* const* d_in, const int* in_sizes, int n_in,
                              void* d_out, int out_size) {
    const float* x = (const float*)d_in[0];
    float* out = (float*)d_out;
    // one CTA per (n, input row): 32 * 512 = 16384 CTAs
    haar_recon_kernel<<<NIMG * S, 128>>>(x, out);
}

// round 17
// speedup vs baseline: 1.0468x; 1.0468x over previous
#include <cuda_runtime.h>
#include <cstdint>

// R17 = R15 + L2 bulk read-prefetch pipeline.
//   2x2 Haar inverse reconstruction:
//   x: (32, 4, 512, 512) f32  ->  out: (32, 1, 1024, 1024) f32
//
// R15 base (confirmed 36.1us ncu, DRAM 72%):
//   one CTA = one input row, 128 thr, 4x LDG.128.cs, 8KB smem stage,
//   one 8KB cp.async.bulk store with L2::evict_first.
// New: CTA b issues cp.async.bulk.prefetch.L2 for the 4 channel rows of
// CTA b+DELTA (one residency generation ahead). Demand reads then hit L2;
// DRAM sees large sequential prefetch bursts instead of latency-paced
// demand dribbles.

#define RCONST 0.70710678118654752440f

static constexpr int S = 512;     // input spatial
static constexpr int NIMG = 32;   // batch
static constexpr int NROWS = NIMG * S;       // 16384 CTAs
static constexpr int DELTA = 2368;           // ~148 SMs x 16 CTAs resident

__device__ __forceinline__ void haar4(float a, float b, float c, float d,
                                      float& o00, float& o01, float& o10, float& o11) {
    float l0 = RCONST * a + RCONST * b;
    float l1 = RCONST * a - RCONST * b;
    float h0 = RCONST * c + RCONST * d;
    float h1 = RCONST * c - RCONST * d;
    o00 = RCONST * l0 + RCONST * h0;
    o01 = RCONST * l0 - RCONST * h0;
    o10 = RCONST * l1 + RCONST * h1;
    o11 = RCONST * l1 - RCONST * h1;
}

__device__ __forceinline__ uint32_t smem_u32(const void* p) {
    uint32_t a;
    asm("{ .reg .u64 t; cvta.to.shared.u64 t, %1; cvt.u32.u64 %0, t; }"
        : "=r"(a) : "l"(p));
    return a;
}

__global__ __launch_bounds__(128)
void haar_recon_kernel(const float* __restrict__ x, float* __restrict__ out) {
    // 2 output rows x 1024 floats = 8KB
    __shared__ alignas(16) float sout[2 * 2 * S];

    unsigned t  = threadIdx.x;    // 0..127 = float4 index within input row
    unsigned b  = blockIdx.x;
    unsigned h  = b & 511;        // input row
    unsigned n  = b >> 9;         // image

    const size_t cs = (size_t)S * S;        // channel stride (floats)
    const size_t cs4 = cs / 4;              // channel stride in float4

    // ---- prefetch the read working set of CTA b+DELTA into L2 ----
    if (t == 0) {
        unsigned g2 = b + DELTA;
        if (g2 < NROWS) {
            unsigned h2 = g2 & 511;
            unsigned n2 = g2 >> 9;
            const float* p0 = x + (size_t)n2 * 4 * cs + (size_t)h2 * S;
            #pragma unroll
            for (int ch = 0; ch < 4; ch++) {
                asm volatile(
                    "cp.async.bulk.prefetch.L2.global [%0], %1;"
                    :: "l"(p0 + (size_t)ch * cs),
                       "r"((unsigned)(S * sizeof(float)))   // 2KB row
                    : "memory");
            }
        }
    }

    const float4* base = (const float4*)(x + (size_t)n * 4 * cs + (size_t)h * S) + t;

    // 4 independent 128-bit streaming loads (MLP=4; should hit L2 now)
    float4 a  = __ldcs(base);
    float4 bb = __ldcs(base + cs4);
    float4 c  = __ldcs(base + 2 * cs4);
    float4 d  = __ldcs(base + 3 * cs4);

    float4 r0a, r0b, r1a, r1b;
    haar4(a.x, bb.x, c.x, d.x, r0a.x, r0a.y, r1a.x, r1a.y);
    haar4(a.y, bb.y, c.y, d.y, r0a.z, r0a.w, r1a.z, r1a.w);
    haar4(a.z, bb.z, c.z, d.z, r0b.x, r0b.y, r1b.x, r1b.y);
    haar4(a.w, bb.w, c.w, d.w, r0b.z, r0b.w, r1b.z, r1b.w);

    // stage: local row 0 = out row 2h, local row 1 = out row 2h+1
    float4* srow0 = (float4*)sout + 2 * t;
    float4* srow1 = (float4*)(sout + 2 * S) + 2 * t;
    srow0[0] = r0a;
    srow0[1] = r0b;
    srow1[0] = r1a;
    srow1[1] = r1b;

    __syncthreads();

    if (t == 0) {
        asm volatile("fence.proxy.async.shared::cta;" ::: "memory");
        // output rows 2h .. 2h+1  (8KB contiguous), evict-first in L2
        float* gdst = out + ((size_t)n * 2 * S + (size_t)2 * h) * (2 * S);
        asm volatile(
            "{\n\t"
            ".reg .b64 pol;\n\t"
            "createpolicy.fractional.L2::evict_first.b64 pol, 1.0;\n\t"
            "cp.async.bulk.global.shared::cta.bulk_group.L2::cache_hint "
            "[%0], [%1], %2, pol;\n\t"
            "}"
            :: "l"(gdst), "r"(smem_u32(sout)),
               "r"((unsigned)(2 * 2 * S * sizeof(float)))
            : "memory");
        asm volatile("cp.async.bulk.commit_group;" ::: "memory");
        asm volatile("cp.async.bulk.wait_group 0;" ::: "memory");
    }
}

extern "C" void kernel_launch(void* const* d_in, const int* in_sizes, int n_in,
                              void* d_out, int out_size) {
    const float* x = (const float*)d_in[0];
    float* out = (float*)d_out;
    // one CTA per (n, input row): 32 * 512 = 16384 CTAs
    haar_recon_kernel<<<NROWS, 128>>>(x, out);
}